// round 9
// baseline (speedup 1.0000x reference)
#include <cuda_runtime.h>
#include <cuda_bf16.h>
#include <cstdint>

#define M_DIM 4096
#define K_DIM 4096
#define N_DIM 11008
#define NG 32            // K/128 groups

// Scratch: dequantized W [N,K] bf16 (90 MB) and x converted to bf16 (33 MB)
__device__ __nv_bfloat16 g_W[(size_t)N_DIM * K_DIM];
__device__ __nv_bfloat16 g_X[(size_t)M_DIM * K_DIM];

// ---------------------------------------------------------------------------
// Kernel 0: convert x f32 -> bf16 (values are exact bf16 already; cast exact)
// ---------------------------------------------------------------------------
__global__ void convert_x_kernel(const float* __restrict__ x) {
    size_t base = ((size_t)blockIdx.x * blockDim.x + threadIdx.x) * 8;
    float4 f0 = *reinterpret_cast<const float4*>(x + base);
    float4 f1 = *reinterpret_cast<const float4*>(x + base + 4);
    __align__(16) __nv_bfloat16 v[8];
    v[0] = __float2bfloat16(f0.x); v[1] = __float2bfloat16(f0.y);
    v[2] = __float2bfloat16(f0.z); v[3] = __float2bfloat16(f0.w);
    v[4] = __float2bfloat16(f1.x); v[5] = __float2bfloat16(f1.y);
    v[6] = __float2bfloat16(f1.z); v[7] = __float2bfloat16(f1.w);
    *reinterpret_cast<uint4*>(g_X + base) = *reinterpret_cast<const uint4*>(v);
}

// ---------------------------------------------------------------------------
// Kernel 1: dequant  w = bf16( bf16((q-8)*s) + z ),  s,z are f32 inputs
// ---------------------------------------------------------------------------
__global__ void dequant_kernel(const int* __restrict__ Wq,
                               const float* __restrict__ scales,
                               const float* __restrict__ zeros) {
    size_t base = ((size_t)blockIdx.x * blockDim.x + threadIdx.x) * 8;
    int n = (int)(base >> 12);          // / 4096
    int k = (int)(base & (K_DIM - 1));
    int g = k >> 7;                     // / 128
    float s = scales[(size_t)n * NG + g];
    float z = zeros [(size_t)n * NG + g];

    const int4* p = reinterpret_cast<const int4*>(Wq + base);
    int4 q0 = p[0];
    int4 q1 = p[1];
    int qs[8] = {q0.x, q0.y, q0.z, q0.w, q1.x, q1.y, q1.z, q1.w};

    __align__(16) __nv_bfloat16 outv[8];
#pragma unroll
    for (int i = 0; i < 8; i++) {
        float t  = (float)qs[i] - 8.0f;                       // exact
        float mf = __bfloat162float(__float2bfloat16(t * s)); // round mul
        outv[i]  = __float2bfloat16(mf + z);                  // round add
    }
    *reinterpret_cast<uint4*>(g_W + base) = *reinterpret_cast<const uint4*>(outv);
}

// ---------------------------------------------------------------------------
// Kernel 2: bf16 TN GEMM  C[M,N] = X[M,K] * W[N,K]^T  (f32 accum)
// Output f32 = bf16-rounded accumulator (matches reference bf16 einsum).
// 128x128x64 tiles, 3-stage cp.async, mma.sync m16n8k16. (decode-validated)
// ---------------------------------------------------------------------------
#define BM 128
#define BN 128
#define BK 64
#define STAGES 3
#define KTILES (K_DIM / BK)     // 64
#define GTHREADS 256

__device__ __forceinline__ uint32_t swz(uint32_t row, uint32_t kchunk) {
    return row * 128u + ((kchunk ^ (row & 7u)) << 4);
}

__device__ __forceinline__ void cp_async16(uint32_t smem, const void* gptr) {
    asm volatile("cp.async.cg.shared.global [%0], [%1], 16;\n"
                 :: "r"(smem), "l"(gptr));
}

__global__ void __launch_bounds__(GTHREADS, 2)
gemm_bf16_kernel(float* __restrict__ C) {
    extern __shared__ __align__(1024) uint8_t smem_raw[];
    const uint32_t smem_u32 = (uint32_t)__cvta_generic_to_shared(smem_raw);

    const int tid  = threadIdx.x;
    const int lane = tid & 31;
    const int warp = tid >> 5;
    const int wm   = warp & 1;
    const int wn   = warp >> 1;

    const int bm = blockIdx.x;
    const int bn = blockIdx.y;

    const __nv_bfloat16* gA = g_X + (size_t)(bm * BM) * K_DIM;
    const __nv_bfloat16* gB = g_W + (size_t)(bn * BN) * K_DIM;

    const uint32_t STAGE_BYTES = 2u * BM * 128u;   // 32768

    auto load_stage = [&](int s, int kt) {
        uint32_t sa = smem_u32 + (uint32_t)s * STAGE_BYTES;
        uint32_t sb = sa + BM * 128u;
        const __nv_bfloat16* ga = gA + (size_t)kt * BK;
        const __nv_bfloat16* gb = gB + (size_t)kt * BK;
#pragma unroll
        for (int i = 0; i < 4; i++) {
            int c   = tid + i * GTHREADS;
            int row = c >> 3;
            int kc  = c & 7;
            cp_async16(sa + swz(row, kc), ga + (size_t)row * K_DIM + kc * 8);
            cp_async16(sb + swz(row, kc), gb + (size_t)row * K_DIM + kc * 8);
        }
    };

    float acc[4][4][4];
#pragma unroll
    for (int i = 0; i < 4; i++)
#pragma unroll
        for (int j = 0; j < 4; j++)
#pragma unroll
            for (int r = 0; r < 4; r++) acc[i][j][r] = 0.0f;

    load_stage(0, 0);
    asm volatile("cp.async.commit_group;\n" ::: "memory");
    load_stage(1, 1);
    asm volatile("cp.async.commit_group;\n" ::: "memory");

    for (int kt = 0; kt < KTILES; kt++) {
        if (kt + 2 < KTILES) load_stage((kt + 2) % STAGES, kt + 2);
        asm volatile("cp.async.commit_group;\n" ::: "memory");
        asm volatile("cp.async.wait_group 2;\n" ::: "memory");
        __syncthreads();

        const int stage = kt % STAGES;
        uint32_t sa = smem_u32 + (uint32_t)stage * STAGE_BYTES;
        uint32_t sb = sa + BM * 128u;

#pragma unroll
        for (int kk = 0; kk < 4; kk++) {
            uint32_t a[4][4];
            uint32_t b[4][2];
#pragma unroll
            for (int im = 0; im < 4; im++) {
                int mrow = wm * 64 + im * 16 + (lane & 15);
                int kc   = 2 * kk + (lane >> 4);
                uint32_t addr = sa + swz((uint32_t)mrow, (uint32_t)kc);
                asm volatile(
                    "ldmatrix.sync.aligned.m8n8.x4.shared.b16 {%0,%1,%2,%3}, [%4];"
                    : "=r"(a[im][0]), "=r"(a[im][1]), "=r"(a[im][2]), "=r"(a[im][3])
                    : "r"(addr));
            }
#pragma unroll
            for (int in2 = 0; in2 < 2; in2++) {
                int nrow = wn * 32 + in2 * 16 + (lane & 15);
                int kc   = 2 * kk + (lane >> 4);
                uint32_t addr = sb + swz((uint32_t)nrow, (uint32_t)kc);
                uint32_t r0, r1, r2, r3;
                asm volatile(
                    "ldmatrix.sync.aligned.m8n8.x4.shared.b16 {%0,%1,%2,%3}, [%4];"
                    : "=r"(r0), "=r"(r1), "=r"(r2), "=r"(r3)
                    : "r"(addr));
                b[in2 * 2 + 0][0] = r0; b[in2 * 2 + 0][1] = r2;
                b[in2 * 2 + 1][0] = r1; b[in2 * 2 + 1][1] = r3;
            }
#pragma unroll
            for (int im = 0; im < 4; im++)
#pragma unroll
                for (int in = 0; in < 4; in++) {
                    asm volatile(
                        "mma.sync.aligned.m16n8k16.row.col.f32.bf16.bf16.f32 "
                        "{%0,%1,%2,%3}, {%4,%5,%6,%7}, {%8,%9}, {%0,%1,%2,%3};\n"
                        : "+f"(acc[im][in][0]), "+f"(acc[im][in][1]),
                          "+f"(acc[im][in][2]), "+f"(acc[im][in][3])
                        : "r"(a[im][0]), "r"(a[im][1]), "r"(a[im][2]), "r"(a[im][3]),
                          "r"(b[in][0]), "r"(b[in][1]));
                }
        }
        __syncthreads();
    }

    // epilogue: f32 output of bf16-rounded values
    const int row0 = bm * BM + wm * 64;
    const int col0 = bn * BN + wn * 32;
#pragma unroll
    for (int im = 0; im < 4; im++) {
#pragma unroll
        for (int in = 0; in < 4; in++) {
            int r = row0 + im * 16 + (lane >> 2);
            int c = col0 + in * 8 + (lane & 3) * 2;
            float2 v0, v1;
            v0.x = __bfloat162float(__float2bfloat16(acc[im][in][0]));
            v0.y = __bfloat162float(__float2bfloat16(acc[im][in][1]));
            v1.x = __bfloat162float(__float2bfloat16(acc[im][in][2]));
            v1.y = __bfloat162float(__float2bfloat16(acc[im][in][3]));
            *reinterpret_cast<float2*>(C + (size_t)r * N_DIM + c) = v0;
            *reinterpret_cast<float2*>(C + (size_t)(r + 8) * N_DIM + c) = v1;
        }
    }
}

// ---------------------------------------------------------------------------
extern "C" void kernel_launch(void* const* d_in, const int* in_sizes, int n_in,
                              void* d_out, int out_size) {
    // All "bf16" tensors are materialized as FLOAT32 buffers (decoded R1-R8):
    const float* x      = (const float*)d_in[0];   // [4096, 4096] f32
    const int*   Wq     = (const int*)d_in[1];     // [11008, 4096] int32
    const float* scales = (const float*)d_in[2];   // [11008, 32] f32
    const float* zeros  = (const float*)d_in[3];   // [11008, 32] f32
    float*       out    = (float*)d_out;           // [4096, 11008] f32

    // Kernel 0: x f32 -> bf16
    {
        size_t thr = (size_t)M_DIM * K_DIM / 8;   // 2,097,152
        convert_x_kernel<<<(unsigned)(thr / 256), 256>>>(x);
    }
    // Kernel 1: dequant
    {
        size_t thr = (size_t)N_DIM * K_DIM / 8;   // 5,636,096
        dequant_kernel<<<(unsigned)(thr / 256), 256>>>(Wq, scales, zeros);
    }
    // Kernel 2: GEMM
    {
        const int smem_bytes = STAGES * 2 * BM * 128;   // 96 KB
        cudaFuncSetAttribute(gemm_bf16_kernel,
                             cudaFuncAttributeMaxDynamicSharedMemorySize,
                             smem_bytes);
        dim3 grid(M_DIM / BM, N_DIM / BN);   // 32 x 86
        gemm_bf16_kernel<<<grid, GTHREADS, smem_bytes>>>(out);
    }
}